// round 3
// baseline (speedup 1.0000x reference)
#include <cuda_runtime.h>
#include <cuda_bf16.h>
#include <cstdint>

#define N_NODES 40000
#define E_EDGES 640000
#define R_REL   8
#define H_DIM   128
#define C_DIM   64

// ---------------- scratch (device globals; no allocation) ----------------
__device__ int   g_cnt_rel[N_NODES * R_REL];   // edge count per (dst, rel)
__device__ int   g_off[N_NODES + 1];           // CSR offsets by dst
__device__ int   g_cursor[N_NODES];            // scatter cursors
__device__ int   g_rowid[E_EDGES];             // sorted: rel*N + src
__device__ float g_scale[E_EDGES];             // sorted: 1/cnt(dst,rel)
__device__ float g_h[N_NODES * H_DIM];         // layer-1 output (post relu)
__device__ float g_hall[R_REL * N_NODES * C_DIM]; // h @ W2[r] for all r

// ---------------- f32x2 helpers (sm_103a packed fp32) ----------------
__device__ __forceinline__ unsigned long long pack2(float x, float y) {
    unsigned long long r;
    asm("mov.b64 %0, {%1, %2};" : "=l"(r) : "f"(x), "f"(y));
    return r;
}
__device__ __forceinline__ void unpack2(unsigned long long v, float& x, float& y) {
    asm("mov.b64 {%0, %1}, %2;" : "=f"(x), "=f"(y) : "l"(v));
}
__device__ __forceinline__ void fma2(unsigned long long& d,
                                     unsigned long long a,
                                     unsigned long long b) {
    asm("fma.rn.f32x2 %0, %1, %2, %0;" : "+l"(d) : "l"(a), "l"(b));
}

// ---------------- kernels ----------------
__global__ void zero_cnt_kernel() {
    int i = blockIdx.x * blockDim.x + threadIdx.x;
    if (i < N_NODES * R_REL) g_cnt_rel[i] = 0;
}

__global__ void count_kernel(const int* __restrict__ edge_index,
                             const int* __restrict__ edge_type) {
    int e = blockIdx.x * blockDim.x + threadIdx.x;
    if (e >= E_EDGES) return;
    int dst = edge_index[E_EDGES + e];
    int et  = edge_type[e];
    atomicAdd(&g_cnt_rel[dst * R_REL + et], 1);
}

// single-block exclusive scan over per-dst degree (derived from g_cnt_rel)
__global__ void scan_kernel() {
    __shared__ int sh[1024];
    __shared__ int s_run;
    const int T = 1024;
    if (threadIdx.x == 0) s_run = 0;
    __syncthreads();
    for (int base = 0; base < N_NODES; base += T) {
        int i = base + threadIdx.x;
        int v = 0;
        if (i < N_NODES) {
            int s = 0;
#pragma unroll
            for (int r = 0; r < R_REL; r++) s += g_cnt_rel[i * R_REL + r];
            v = s;
        }
        sh[threadIdx.x] = v;
        __syncthreads();
        for (int ofs = 1; ofs < T; ofs <<= 1) {
            int t = (threadIdx.x >= ofs) ? sh[threadIdx.x - ofs] : 0;
            __syncthreads();
            sh[threadIdx.x] += t;
            __syncthreads();
        }
        int incl = sh[threadIdx.x];
        int excl = incl - v;
        int run = s_run;
        if (i < N_NODES) {
            g_off[i]    = run + excl;
            g_cursor[i] = run + excl;
        }
        __syncthreads();
        if (threadIdx.x == T - 1) s_run = run + incl;
        __syncthreads();
    }
    if (threadIdx.x == 0) g_off[N_NODES] = s_run;  // == E
}

__global__ void permute_kernel(const int* __restrict__ edge_index,
                               const int* __restrict__ edge_type) {
    int e = blockIdx.x * blockDim.x + threadIdx.x;
    if (e >= E_EDGES) return;
    int src = edge_index[e];
    int dst = edge_index[E_EDGES + e];
    int et  = edge_type[e];
    int pos = atomicAdd(&g_cursor[dst], 1);
    g_rowid[pos] = et * N_NODES + src;
    g_scale[pos] = 1.0f / (float)g_cnt_rel[dst * R_REL + et];
}

// layer 1: h[n] = relu( sum_e scale_e * W1[rowid_e, :] + root1[n] + b1 )
// one block (128 threads) per destination node; thread t owns feature t.
__global__ void agg1_kernel(const float* __restrict__ W1,
                            const float* __restrict__ root1,
                            const float* __restrict__ b1) {
    int n = blockIdx.x;
    int t = threadIdx.x;
    int beg = g_off[n], end = g_off[n + 1];
    float acc = 0.0f;
    int i = beg;
    // 2-wide software pipeline for MLP
    for (; i + 1 < end; i += 2) {
        int   r0 = g_rowid[i],     r1 = g_rowid[i + 1];
        float s0 = g_scale[i],     s1 = g_scale[i + 1];
        float v0 = __ldg(&W1[r0 * H_DIM + t]);
        float v1 = __ldg(&W1[r1 * H_DIM + t]);
        acc = fmaf(s0, v0, acc);
        acc = fmaf(s1, v1, acc);
    }
    if (i < end) {
        acc = fmaf(g_scale[i], __ldg(&W1[g_rowid[i] * H_DIM + t]), acc);
    }
    float v = acc + root1[n * H_DIM + t] + b1[t];
    g_h[n * H_DIM + t] = fmaxf(v, 0.0f);
}

// Batched GEMM: for r<8: h_all[r] = h @ W2[r]; for r==8: out = h @ root2 + b2
// M tile = 128 rows, full C=64 columns, K staged in chunks of 32.
// 256 threads: tx = lane%16 covers 4 cols, ty = tid/16 covers 8 rows.
__global__ __launch_bounds__(256) void gemm_kernel(const float* __restrict__ W2,
                                                   const float* __restrict__ root2,
                                                   const float* __restrict__ b2,
                                                   float* __restrict__ out) {
    __shared__ float As[128 * 33];   // [row][k], padded
    __shared__ float Bs[32 * 64];    // [k][col]

    const int r = blockIdx.y;
    const float* Bmat = (r < 8) ? (W2 + r * H_DIM * C_DIM) : root2;
    const int rowBase = blockIdx.x * 128;
    const int tid = threadIdx.x;
    const int tx = tid & 15;        // 0..15 -> cols tx*4..tx*4+3
    const int ty = tid >> 4;        // 0..15 -> rows ty*8..ty*8+7

    unsigned long long acc[8][2];
#pragma unroll
    for (int i = 0; i < 8; i++) { acc[i][0] = pack2(0.f, 0.f); acc[i][1] = pack2(0.f, 0.f); }

    for (int kb = 0; kb < H_DIM; kb += 32) {
        // load A tile: 128 rows x 32 k (1024 float4, 4 per thread)
#pragma unroll
        for (int i = 0; i < 4; i++) {
            int f   = tid + 256 * i;          // float4 index
            int row = f >> 3;                 // 8 float4 per row
            int k4  = f & 7;
            float4 v = make_float4(0.f, 0.f, 0.f, 0.f);
            int grow = rowBase + row;
            if (grow < N_NODES)
                v = *reinterpret_cast<const float4*>(&g_h[grow * H_DIM + kb + k4 * 4]);
            As[row * 33 + k4 * 4 + 0] = v.x;
            As[row * 33 + k4 * 4 + 1] = v.y;
            As[row * 33 + k4 * 4 + 2] = v.z;
            As[row * 33 + k4 * 4 + 3] = v.w;
        }
        // load B tile: 32 k x 64 cols (512 float4, 2 per thread)
#pragma unroll
        for (int i = 0; i < 2; i++) {
            int f  = tid + 256 * i;
            int k  = f >> 4;                  // 16 float4 per k-row
            int c4 = f & 15;
            float4 v = *reinterpret_cast<const float4*>(&Bmat[(kb + k) * C_DIM + c4 * 4]);
            *reinterpret_cast<float4*>(&Bs[k * 64 + c4 * 4]) = v;
        }
        __syncthreads();

#pragma unroll
        for (int k = 0; k < 32; k++) {
            float b0 = Bs[k * 64 + tx * 4 + 0];
            float b1v = Bs[k * 64 + tx * 4 + 1];
            float b2v = Bs[k * 64 + tx * 4 + 2];
            float b3 = Bs[k * 64 + tx * 4 + 3];
            unsigned long long b01 = pack2(b0, b1v);
            unsigned long long b23 = pack2(b2v, b3);
#pragma unroll
            for (int i = 0; i < 8; i++) {
                float av = As[(ty * 8 + i) * 33 + k];
                unsigned long long a2 = pack2(av, av);
                fma2(acc[i][0], a2, b01);
                fma2(acc[i][1], a2, b23);
            }
        }
        __syncthreads();
    }

    // store
#pragma unroll
    for (int i = 0; i < 8; i++) {
        int row = rowBase + ty * 8 + i;
        if (row >= N_NODES) continue;
        float c0, c1, c2, c3;
        unpack2(acc[i][0], c0, c1);
        unpack2(acc[i][1], c2, c3);
        int col = tx * 4;
        if (r < 8) {
            float4 v = make_float4(c0, c1, c2, c3);
            *reinterpret_cast<float4*>(&g_hall[(r * N_NODES + row) * C_DIM + col]) = v;
        } else {
            float4 v = make_float4(c0 + b2[col + 0], c1 + b2[col + 1],
                                   c2 + b2[col + 2], c3 + b2[col + 3]);
            *reinterpret_cast<float4*>(&out[row * C_DIM + col]) = v;
        }
    }
}

// layer 2 aggregation: out[n] += sum_e scale_e * h_all[rowid_e, :]
// one block (64 threads) per destination node
__global__ void agg2_kernel(float* __restrict__ out) {
    int n = blockIdx.x;
    int t = threadIdx.x;
    int beg = g_off[n], end = g_off[n + 1];
    float acc = 0.0f;
    int i = beg;
    for (; i + 1 < end; i += 2) {
        int   r0 = g_rowid[i],     r1 = g_rowid[i + 1];
        float s0 = g_scale[i],     s1 = g_scale[i + 1];
        float v0 = __ldg(&g_hall[r0 * C_DIM + t]);
        float v1 = __ldg(&g_hall[r1 * C_DIM + t]);
        acc = fmaf(s0, v0, acc);
        acc = fmaf(s1, v1, acc);
    }
    if (i < end) {
        acc = fmaf(g_scale[i], __ldg(&g_hall[g_rowid[i] * C_DIM + t]), acc);
    }
    out[n * C_DIM + t] += acc;
}

// ---------------- launch ----------------
extern "C" void kernel_launch(void* const* d_in, const int* in_sizes, int n_in,
                              void* d_out, int out_size) {
    const int*   edge_index = (const int*)d_in[0];   // (2, E)
    const int*   edge_type  = (const int*)d_in[1];   // (E,)
    const float* W1         = (const float*)d_in[2]; // (R, N, H)
    const float* root1      = (const float*)d_in[3]; // (N, H)
    const float* b1         = (const float*)d_in[4]; // (H,)
    const float* W2         = (const float*)d_in[5]; // (R, H, C)
    const float* root2      = (const float*)d_in[6]; // (H, C)
    const float* b2         = (const float*)d_in[7]; // (C,)
    float*       out        = (float*)d_out;         // (N, C)

    zero_cnt_kernel<<<(N_NODES * R_REL + 255) / 256, 256>>>();
    count_kernel<<<(E_EDGES + 255) / 256, 256>>>(edge_index, edge_type);
    scan_kernel<<<1, 1024>>>();
    permute_kernel<<<(E_EDGES + 255) / 256, 256>>>(edge_index, edge_type);
    agg1_kernel<<<N_NODES, H_DIM>>>(W1, root1, b1);
    dim3 ggrid((N_NODES + 127) / 128, 9);
    gemm_kernel<<<ggrid, 256>>>(W2, root2, b2, out);
    agg2_kernel<<<N_NODES, C_DIM>>>(out);
}

// round 4
// speedup vs baseline: 1.2722x; 1.2722x over previous
#include <cuda_runtime.h>
#include <cuda_bf16.h>
#include <cstdint>

#define N_NODES 40000
#define E_EDGES 640000
#define R_REL   8
#define H_DIM   128
#define C_DIM   64

// ---------------- scratch (device globals; no allocation) ----------------
__device__ int                g_cnt_rel[N_NODES * R_REL]; // edge count per (dst, rel)
__device__ int                g_off[N_NODES + 1];         // CSR offsets by dst
__device__ int                g_cursor[N_NODES];          // scatter cursors
__device__ int                g_bsum[64];                 // per-block scan partials
__device__ int                g_boff[64];                 // scanned partials
__device__ unsigned long long g_edge[E_EDGES];            // packed (scale<<32 | rowid), sorted by dst
__device__ float              g_h[N_NODES * H_DIM];       // layer-1 output (post relu)
__device__ float              g_hall[(size_t)R_REL * N_NODES * C_DIM]; // h @ W2[r]

// ---------------- f32x2 helpers (sm_103a packed fp32) ----------------
__device__ __forceinline__ void unpack2(unsigned long long v, float& x, float& y) {
    asm("mov.b64 {%0, %1}, %2;" : "=f"(x), "=f"(y) : "l"(v));
}
__device__ __forceinline__ void fma2(unsigned long long& d,
                                     unsigned long long a,
                                     unsigned long long b) {
    asm("fma.rn.f32x2 %0, %1, %2, %0;" : "+l"(d) : "l"(a), "l"(b));
}

// ---------------- build CSR ----------------
__global__ void zero_cnt_kernel() {
    int i = blockIdx.x * blockDim.x + threadIdx.x;
    if (i < N_NODES * R_REL) g_cnt_rel[i] = 0;
}

__global__ void count_kernel(const int* __restrict__ edge_index,
                             const int* __restrict__ edge_type) {
    int e = blockIdx.x * blockDim.x + threadIdx.x;
    if (e >= E_EDGES) return;
    int dst = edge_index[E_EDGES + e];
    int et  = edge_type[e];
    atomicAdd(&g_cnt_rel[dst * R_REL + et], 1);
}

// scan pass 1: per-block local exclusive scan of per-node degree; block sums out
__global__ void scan1_kernel() {
    __shared__ int sh[1024];
    int t = threadIdx.x;
    int i = blockIdx.x * 1024 + t;
    int deg = 0;
    if (i < N_NODES) {
        const int4* p = reinterpret_cast<const int4*>(&g_cnt_rel[i * R_REL]);
        int4 a = p[0], b = p[1];
        deg = a.x + a.y + a.z + a.w + b.x + b.y + b.z + b.w;
    }
    sh[t] = deg;
    __syncthreads();
    for (int ofs = 1; ofs < 1024; ofs <<= 1) {
        int v = (t >= ofs) ? sh[t - ofs] : 0;
        __syncthreads();
        sh[t] += v;
        __syncthreads();
    }
    if (i < N_NODES) g_off[i] = sh[t] - deg;   // local exclusive
    if (t == 1023)   g_bsum[blockIdx.x] = sh[t];
}

// scan pass 2: scan the (<=40) block sums
__global__ void scan2_kernel() {
    __shared__ int sh[64];
    int t = threadIdx.x;
    int v = (t < 40) ? g_bsum[t] : 0;
    sh[t] = v;
    __syncthreads();
    for (int ofs = 1; ofs < 64; ofs <<= 1) {
        int u = (t >= ofs) ? sh[t - ofs] : 0;
        __syncthreads();
        sh[t] += u;
        __syncthreads();
    }
    g_boff[t] = sh[t] - v;                     // exclusive
}

// scan pass 3: add block offsets, init cursors
__global__ void scan3_kernel() {
    int t = threadIdx.x;
    int i = blockIdx.x * 1024 + t;
    if (i < N_NODES) {
        int o = g_off[i] + g_boff[blockIdx.x];
        g_off[i]    = o;
        g_cursor[i] = o;
    }
    if (i == 0) g_off[N_NODES] = E_EDGES;
}

__global__ void permute_kernel(const int* __restrict__ edge_index,
                               const int* __restrict__ edge_type) {
    int e = blockIdx.x * blockDim.x + threadIdx.x;
    if (e >= E_EDGES) return;
    int src = edge_index[e];
    int dst = edge_index[E_EDGES + e];
    int et  = edge_type[e];
    int pos = atomicAdd(&g_cursor[dst], 1);
    int cnt = g_cnt_rel[dst * R_REL + et];
    float sc = 1.0f / (float)cnt;
    unsigned rowid = (unsigned)(et * N_NODES + src);
    g_edge[pos] = ((unsigned long long)__float_as_uint(sc) << 32) | rowid;
}

// ---------------- layer 1 aggregation: warp per node, float4 per lane -------
// h[n] = relu( sum_e scale_e * W1[rowid_e, :] + root1[n] + b1 )
__global__ __launch_bounds__(256) void agg1_kernel(const float* __restrict__ W1,
                                                   const float* __restrict__ root1,
                                                   const float* __restrict__ b1) {
    int wid  = threadIdx.x >> 5;
    int lane = threadIdx.x & 31;
    int n = blockIdx.x * 8 + wid;
    if (n >= N_NODES) return;
    int beg = g_off[n], end = g_off[n + 1];

    float4 acc = make_float4(0.f, 0.f, 0.f, 0.f);
    for (int base = beg; base < end; base += 32) {
        int e = base + lane;
        unsigned long long pk = (e < end) ? g_edge[e] : 0ull;
        int m = end - base; if (m > 32) m = 32;
        for (int j = 0; j < m; j++) {
            unsigned long long pj = __shfl_sync(0xffffffffu, pk, j);
            int   rowid = (int)(pj & 0xffffffffu);
            float sc    = __uint_as_float((unsigned)(pj >> 32));
            float4 v = *reinterpret_cast<const float4*>(
                &W1[(size_t)rowid * H_DIM + lane * 4]);
            acc.x = fmaf(sc, v.x, acc.x);
            acc.y = fmaf(sc, v.y, acc.y);
            acc.z = fmaf(sc, v.z, acc.z);
            acc.w = fmaf(sc, v.w, acc.w);
        }
    }
    float4 rt = *reinterpret_cast<const float4*>(&root1[(size_t)n * H_DIM + lane * 4]);
    float4 bb = *reinterpret_cast<const float4*>(&b1[lane * 4]);
    float4 o;
    o.x = fmaxf(acc.x + rt.x + bb.x, 0.f);
    o.y = fmaxf(acc.y + rt.y + bb.y, 0.f);
    o.z = fmaxf(acc.z + rt.z + bb.z, 0.f);
    o.w = fmaxf(acc.w + rt.w + bb.w, 0.f);
    *reinterpret_cast<float4*>(&g_h[(size_t)n * H_DIM + lane * 4]) = o;
}

// ---------------- batched GEMM, K-paired f32x2 ------------------------------
// r<8: h_all[r] = h @ W2[r];  r==8: out = h @ root2 + b2
// tile: 128 rows x 64 cols, 128 threads, 8x8 outputs/thread, K chunk 32.
// A smem [row][k] stride 34 floats; B smem transposed [col][k] stride 34.
// acc pairs accumulate (even-k, odd-k) partial sums; horizontal add at end.
#define AS_STRIDE 34
__global__ __launch_bounds__(128) void gemm_kernel(const float* __restrict__ W2,
                                                   const float* __restrict__ root2,
                                                   const float* __restrict__ bias2,
                                                   float* __restrict__ out) {
    __shared__ float As[128 * AS_STRIDE];
    __shared__ float Bs[64 * AS_STRIDE];

    const int r = blockIdx.y;
    const float* Bmat = (r < 8) ? (W2 + (size_t)r * H_DIM * C_DIM) : root2;
    const int rowBase = blockIdx.x * 128;
    const int tid = threadIdx.x;
    const int tx = tid & 7;    // col = tx + 8*j
    const int ty = tid >> 3;   // row = ty + 16*i   (ty in 0..15)

    unsigned long long acc[8][8];
#pragma unroll
    for (int i = 0; i < 8; i++)
#pragma unroll
        for (int j = 0; j < 8; j++) acc[i][j] = 0ull;

    const unsigned long long* Asu = reinterpret_cast<const unsigned long long*>(As);
    const unsigned long long* Bsu = reinterpret_cast<const unsigned long long*>(Bs);

    for (int kb = 0; kb < H_DIM; kb += 32) {
        // A tile: 128 rows x 32 k  (1024 float4, 8 per thread)
#pragma unroll
        for (int i = 0; i < 8; i++) {
            int f   = tid + 128 * i;
            int row = f >> 3;
            int k4  = f & 7;
            float4 v = make_float4(0.f, 0.f, 0.f, 0.f);
            int grow = rowBase + row;
            if (grow < N_NODES)
                v = *reinterpret_cast<const float4*>(&g_h[(size_t)grow * H_DIM + kb + k4 * 4]);
            As[row * AS_STRIDE + k4 * 4 + 0] = v.x;
            As[row * AS_STRIDE + k4 * 4 + 1] = v.y;
            As[row * AS_STRIDE + k4 * 4 + 2] = v.z;
            As[row * AS_STRIDE + k4 * 4 + 3] = v.w;
        }
        // B tile transposed: Bs[col][k] <- Bmat[kb+k][col]  (2048 scalars, 16/thread)
#pragma unroll
        for (int i = 0; i < 16; i++) {
            int idx = tid + 128 * i;
            int col = idx & 63;
            int k   = idx >> 6;
            Bs[col * AS_STRIDE + k] = Bmat[(size_t)(kb + k) * C_DIM + col];
        }
        __syncthreads();

#pragma unroll 4
        for (int kk = 0; kk < 16; kk++) {   // kk indexes k-pairs
            unsigned long long a2[8], b2[8];
#pragma unroll
            for (int i = 0; i < 8; i++)
                a2[i] = Asu[(ty + 16 * i) * (AS_STRIDE / 2) + kk];
#pragma unroll
            for (int j = 0; j < 8; j++)
                b2[j] = Bsu[(tx + 8 * j) * (AS_STRIDE / 2) + kk];
#pragma unroll
            for (int i = 0; i < 8; i++)
#pragma unroll
                for (int j = 0; j < 8; j++)
                    fma2(acc[i][j], a2[i], b2[j]);
        }
        __syncthreads();
    }

    // epilogue: horizontal add of (even,odd) partials, store
#pragma unroll
    for (int i = 0; i < 8; i++) {
        int row = rowBase + ty + 16 * i;
        if (row >= N_NODES) continue;
#pragma unroll
        for (int j = 0; j < 8; j++) {
            int col = tx + 8 * j;
            float lo, hi;
            unpack2(acc[i][j], lo, hi);
            float val = lo + hi;
            if (r < 8)
                g_hall[((size_t)r * N_NODES + row) * C_DIM + col] = val;
            else
                out[(size_t)row * C_DIM + col] = val + bias2[col];
        }
    }
}

// ---------------- layer 2 aggregation: warp per node, float2 per lane -------
__global__ __launch_bounds__(256) void agg2_kernel(float* __restrict__ out) {
    int wid  = threadIdx.x >> 5;
    int lane = threadIdx.x & 31;
    int n = blockIdx.x * 8 + wid;
    if (n >= N_NODES) return;
    int beg = g_off[n], end = g_off[n + 1];
    if (beg == end) return;

    float2 acc = make_float2(0.f, 0.f);
    for (int base = beg; base < end; base += 32) {
        int e = base + lane;
        unsigned long long pk = (e < end) ? g_edge[e] : 0ull;
        int m = end - base; if (m > 32) m = 32;
        for (int j = 0; j < m; j++) {
            unsigned long long pj = __shfl_sync(0xffffffffu, pk, j);
            int   rowid = (int)(pj & 0xffffffffu);
            float sc    = __uint_as_float((unsigned)(pj >> 32));
            float2 v = *reinterpret_cast<const float2*>(
                &g_hall[(size_t)rowid * C_DIM + lane * 2]);
            acc.x = fmaf(sc, v.x, acc.x);
            acc.y = fmaf(sc, v.y, acc.y);
        }
    }
    float2* po = reinterpret_cast<float2*>(&out[(size_t)n * C_DIM + lane * 2]);
    float2 cur = *po;
    cur.x += acc.x;
    cur.y += acc.y;
    *po = cur;
}

// ---------------- launch ----------------
extern "C" void kernel_launch(void* const* d_in, const int* in_sizes, int n_in,
                              void* d_out, int out_size) {
    const int*   edge_index = (const int*)d_in[0];   // (2, E)
    const int*   edge_type  = (const int*)d_in[1];   // (E,)
    const float* W1         = (const float*)d_in[2]; // (R, N, H)
    const float* root1      = (const float*)d_in[3]; // (N, H)
    const float* b1         = (const float*)d_in[4]; // (H,)
    const float* W2         = (const float*)d_in[5]; // (R, H, C)
    const float* root2      = (const float*)d_in[6]; // (H, C)
    const float* b2         = (const float*)d_in[7]; // (C,)
    float*       out        = (float*)d_out;         // (N, C)

    zero_cnt_kernel<<<(N_NODES * R_REL + 255) / 256, 256>>>();
    count_kernel<<<(E_EDGES + 255) / 256, 256>>>(edge_index, edge_type);
    scan1_kernel<<<40, 1024>>>();
    scan2_kernel<<<1, 64>>>();
    scan3_kernel<<<40, 1024>>>();
    permute_kernel<<<(E_EDGES + 255) / 256, 256>>>(edge_index, edge_type);
    agg1_kernel<<<5000, 256>>>(W1, root1, b1);
    dim3 ggrid((N_NODES + 127) / 128, 9);
    gemm_kernel<<<ggrid, 128>>>(W2, root2, b2, out);
    agg2_kernel<<<5000, 256>>>(out);
}

// round 9
// speedup vs baseline: 1.7670x; 1.3890x over previous
#include <cuda_runtime.h>
#include <cuda_bf16.h>
#include <cstdint>

#define N_NODES 40000
#define E_EDGES 640000
#define R_REL   8
#define H_DIM   128
#define C_DIM   64
#define TILES   313          // ceil(40000/128)
#define ROWS_PAD (TILES * 128)

// ---------------- scratch (device globals; no allocation) ----------------
__device__ int                g_cnt_rel[N_NODES * R_REL];
__device__ int                g_off[N_NODES + 1];
__device__ int                g_cursor[N_NODES];
__device__ int                g_bsum[64];
__device__ int                g_boff[64];
__device__ unsigned long long g_edge[E_EDGES];            // (scale<<32 | rowid) sorted by dst
__device__ float              g_hall[(size_t)R_REL * N_NODES * C_DIM];
// bf16 split images of h (A operand), row-major [row][k], packed bf16x2 words
__device__ __align__(16) uint32_t g_Ahi[(size_t)ROWS_PAD * 64];
__device__ __align__(16) uint32_t g_Alo[(size_t)ROWS_PAD * 64];
// bf16 split images of W2[r]/root2 (B operand), [r][col][k] packed bf16x2 words
__device__ __align__(16) uint32_t g_Bhi[9 * 64 * 64];
__device__ __align__(16) uint32_t g_Blo[9 * 64 * 64];

// ---------------- helpers ----------------
__device__ __forceinline__ uint32_t pk_hi2(float a, float b, float& la, float& lb) {
    __nv_bfloat16 ha = __float2bfloat16(a);
    __nv_bfloat16 hb = __float2bfloat16(b);
    la = a - __bfloat162float(ha);
    lb = b - __bfloat162float(hb);
    __nv_bfloat162 t(ha, hb);            // ha -> low half
    return *reinterpret_cast<uint32_t*>(&t);
}
__device__ __forceinline__ uint32_t pk2(float a, float b) {
    __nv_bfloat162 t = __floats2bfloat162_rn(a, b);   // a -> low half
    return *reinterpret_cast<uint32_t*>(&t);
}
__device__ __forceinline__ void mma16816(float* c, const uint32_t* a, const uint32_t* b) {
    asm volatile(
        "mma.sync.aligned.m16n8k16.row.col.f32.bf16.bf16.f32 "
        "{%0,%1,%2,%3}, {%4,%5,%6,%7}, {%8,%9}, {%0,%1,%2,%3};"
        : "+f"(c[0]), "+f"(c[1]), "+f"(c[2]), "+f"(c[3])
        : "r"(a[0]), "r"(a[1]), "r"(a[2]), "r"(a[3]), "r"(b[0]), "r"(b[1]));
}

// ---------------- build CSR ----------------
__global__ void zero_cnt_kernel() {
    int i = blockIdx.x * blockDim.x + threadIdx.x;
    if (i < N_NODES * R_REL) g_cnt_rel[i] = 0;
}

__global__ void count_kernel(const int* __restrict__ edge_index,
                             const int* __restrict__ edge_type) {
    int e = blockIdx.x * blockDim.x + threadIdx.x;
    if (e >= E_EDGES) return;
    int dst = edge_index[E_EDGES + e];
    int et  = edge_type[e];
    atomicAdd(&g_cnt_rel[dst * R_REL + et], 1);
}

__global__ void scan1_kernel() {
    __shared__ int sh[1024];
    int t = threadIdx.x;
    int i = blockIdx.x * 1024 + t;
    int deg = 0;
    if (i < N_NODES) {
        const int4* p = reinterpret_cast<const int4*>(&g_cnt_rel[i * R_REL]);
        int4 a = p[0], b = p[1];
        deg = a.x + a.y + a.z + a.w + b.x + b.y + b.z + b.w;
    }
    sh[t] = deg;
    __syncthreads();
    for (int ofs = 1; ofs < 1024; ofs <<= 1) {
        int v = (t >= ofs) ? sh[t - ofs] : 0;
        __syncthreads();
        sh[t] += v;
        __syncthreads();
    }
    if (i < N_NODES) g_off[i] = sh[t] - deg;
    if (t == 1023)   g_bsum[blockIdx.x] = sh[t];
}

__global__ void scan2_kernel() {
    __shared__ int sh[64];
    int t = threadIdx.x;
    int v = (t < 40) ? g_bsum[t] : 0;
    sh[t] = v;
    __syncthreads();
    for (int ofs = 1; ofs < 64; ofs <<= 1) {
        int u = (t >= ofs) ? sh[t - ofs] : 0;
        __syncthreads();
        sh[t] += u;
        __syncthreads();
    }
    g_boff[t] = sh[t] - v;
}

__global__ void scan3_kernel() {
    int t = threadIdx.x;
    int i = blockIdx.x * 1024 + t;
    if (i < N_NODES) {
        int o = g_off[i] + g_boff[blockIdx.x];
        g_off[i]    = o;
        g_cursor[i] = o;
    }
    if (i == 0) g_off[N_NODES] = E_EDGES;
}

__global__ void permute_kernel(const int* __restrict__ edge_index,
                               const int* __restrict__ edge_type) {
    int e = blockIdx.x * blockDim.x + threadIdx.x;
    if (e >= E_EDGES) return;
    int src = edge_index[e];
    int dst = edge_index[E_EDGES + e];
    int et  = edge_type[e];
    int pos = atomicAdd(&g_cursor[dst], 1);
    int cnt = g_cnt_rel[dst * R_REL + et];
    float sc = 1.0f / (float)cnt;
    unsigned rowid = (unsigned)(et * N_NODES + src);
    g_edge[pos] = ((unsigned long long)__float_as_uint(sc) << 32) | rowid;
}

// ---------------- B prep: W2[r]/root2 -> [r][col][k] bf16 hi/lo --------------
__global__ void w2prep_kernel(const float* __restrict__ W2,
                              const float* __restrict__ root2) {
    int idx = blockIdx.x * blockDim.x + threadIdx.x;   // 9*64*64 k-pairs
    if (idx >= 9 * 64 * 64) return;
    int r   = idx >> 12;
    int rem = idx & 4095;
    int n   = rem >> 6;        // output col
    int k2  = rem & 63;        // k-pair index
    int k   = k2 * 2;
    const float* mat = (r < 8) ? (W2 + (size_t)r * H_DIM * C_DIM) : root2;
    float x0 = mat[(size_t)k * C_DIM + n];
    float x1 = mat[(size_t)(k + 1) * C_DIM + n];
    float l0, l1;
    uint32_t hi = pk_hi2(x0, x1, l0, l1);
    uint32_t lo = pk2(l0, l1);
    g_Bhi[idx] = hi;
    g_Blo[idx] = lo;
}

// ---------------- layer 1 aggregation: warp per node -------------------------
// h[n] = relu(sum scale*W1[rowid,:] + root1[n] + b1); emit bf16 hi/lo rows
__global__ __launch_bounds__(256) void agg1_kernel(const float* __restrict__ W1,
                                                   const float* __restrict__ root1,
                                                   const float* __restrict__ b1) {
    int wid  = threadIdx.x >> 5;
    int lane = threadIdx.x & 31;
    int n = blockIdx.x * 8 + wid;
    if (n >= N_NODES) return;
    int beg = g_off[n], end = g_off[n + 1];

    float4 acc = make_float4(0.f, 0.f, 0.f, 0.f);
    for (int base = beg; base < end; base += 32) {
        int e = base + lane;
        unsigned long long pk = (e < end) ? g_edge[e] : 0ull;
        int m = end - base; if (m > 32) m = 32;
        for (int j = 0; j < m; j++) {
            unsigned long long pj = __shfl_sync(0xffffffffu, pk, j);
            int   rowid = (int)(pj & 0xffffffffu);
            float sc    = __uint_as_float((unsigned)(pj >> 32));
            float4 v = *reinterpret_cast<const float4*>(
                &W1[(size_t)rowid * H_DIM + lane * 4]);
            acc.x = fmaf(sc, v.x, acc.x);
            acc.y = fmaf(sc, v.y, acc.y);
            acc.z = fmaf(sc, v.z, acc.z);
            acc.w = fmaf(sc, v.w, acc.w);
        }
    }
    float4 rt = *reinterpret_cast<const float4*>(&root1[(size_t)n * H_DIM + lane * 4]);
    float4 bb = *reinterpret_cast<const float4*>(&b1[lane * 4]);
    float4 o;
    o.x = fmaxf(acc.x + rt.x + bb.x, 0.f);
    o.y = fmaxf(acc.y + rt.y + bb.y, 0.f);
    o.z = fmaxf(acc.z + rt.z + bb.z, 0.f);
    o.w = fmaxf(acc.w + rt.w + bb.w, 0.f);

    float l0, l1, l2, l3;
    uint32_t h01 = pk_hi2(o.x, o.y, l0, l1);
    uint32_t h23 = pk_hi2(o.z, o.w, l2, l3);
    uint32_t w01 = pk2(l0, l1);
    uint32_t w23 = pk2(l2, l3);
    size_t base = (size_t)n * 64 + lane * 2;
    g_Ahi[base]     = h01;
    g_Ahi[base + 1] = h23;
    g_Alo[base]     = w01;
    g_Alo[base + 1] = w23;
}

// ---------------- bf16-split HMMA batched GEMM -------------------------------
// block = 128-row tile of h, loops r=0..8 with A smem-resident.
// D(128x64 f32) = A_hi*B_hi + A_hi*B_lo + A_lo*B_hi   (each K=128)
// 8 warps: warp_m = wid>>1 (32 rows), warp_n = wid&1 (32 cols).
// smem rows stride 272B (68 words == 4 mod 32 banks -> conflict-free frags).
#define ROW_B   272
#define A_HI_O  0
#define A_LO_O  34816
#define B_HI_O  69632
#define B_LO_O  87040
#define SM_TOT  104448

__global__ __launch_bounds__(256) void gemm_kernel(const float* __restrict__ bias2,
                                                   float* __restrict__ out) {
    extern __shared__ char sm[];
    const int tid    = threadIdx.x;
    const int lane   = tid & 31;
    const int wid    = tid >> 5;
    const int warp_m = wid >> 1;
    const int warp_n = wid & 1;
    const int g      = lane >> 2;
    const int t      = lane & 3;
    const int tile   = blockIdx.x;

    // ---- load A (hi+lo) into smem: 2048 float4 per image, 8/thread ----
    {
        const float4* sH = reinterpret_cast<const float4*>(g_Ahi + (size_t)tile * 128 * 64);
        const float4* sL = reinterpret_cast<const float4*>(g_Alo + (size_t)tile * 128 * 64);
#pragma unroll
        for (int i = 0; i < 8; i++) {
            int f    = tid + 256 * i;
            int row  = f >> 4;          // 16 float4 per 256B row
            int ch   = f & 15;
            *reinterpret_cast<float4*>(sm + A_HI_O + row * ROW_B + ch * 16) = sH[f];
            *reinterpret_cast<float4*>(sm + A_LO_O + row * ROW_B + ch * 16) = sL[f];
        }
    }

    for (int r = 0; r < 9; r++) {
        // ---- load B_r (hi+lo): 1024 float4 per image, 4/thread ----
        {
            const float4* sH = reinterpret_cast<const float4*>(g_Bhi + r * 4096);
            const float4* sL = reinterpret_cast<const float4*>(g_Blo + r * 4096);
#pragma unroll
            for (int i = 0; i < 4; i++) {
                int f   = tid + 256 * i;
                int col = f >> 4;
                int ch  = f & 15;
                *reinterpret_cast<float4*>(sm + B_HI_O + col * ROW_B + ch * 16) = sH[f];
                *reinterpret_cast<float4*>(sm + B_LO_O + col * ROW_B + ch * 16) = sL[f];
            }
        }
        __syncthreads();

        float acc[2][4][4];
#pragma unroll
        for (int m = 0; m < 2; m++)
#pragma unroll
            for (int n = 0; n < 4; n++)
#pragma unroll
                for (int c = 0; c < 4; c++) acc[m][n][c] = 0.f;

#pragma unroll
        for (int k8 = 0; k8 < 8; k8++) {
            const int kbyte = (k8 * 16 + t * 2) * 2;   // byte offset of this thread's k-pair
            uint32_t ahi[2][4], alo[2][4];
#pragma unroll
            for (int m = 0; m < 2; m++) {
                const char* p = sm + (warp_m * 32 + m * 16 + g) * ROW_B + kbyte;
                ahi[m][0] = *(const uint32_t*)(p + A_HI_O);
                ahi[m][1] = *(const uint32_t*)(p + A_HI_O + 8 * ROW_B);
                ahi[m][2] = *(const uint32_t*)(p + A_HI_O + 16);
                ahi[m][3] = *(const uint32_t*)(p + A_HI_O + 8 * ROW_B + 16);
                alo[m][0] = *(const uint32_t*)(p + A_LO_O);
                alo[m][1] = *(const uint32_t*)(p + A_LO_O + 8 * ROW_B);
                alo[m][2] = *(const uint32_t*)(p + A_LO_O + 16);
                alo[m][3] = *(const uint32_t*)(p + A_LO_O + 8 * ROW_B + 16);
            }
            uint32_t bhi[4][2], blo[4][2];
#pragma unroll
            for (int n = 0; n < 4; n++) {
                const char* p = sm + (warp_n * 32 + n * 8 + g) * ROW_B + kbyte;
                bhi[n][0] = *(const uint32_t*)(p + B_HI_O);
                bhi[n][1] = *(const uint32_t*)(p + B_HI_O + 16);
                blo[n][0] = *(const uint32_t*)(p + B_LO_O);
                blo[n][1] = *(const uint32_t*)(p + B_LO_O + 16);
            }
#pragma unroll
            for (int m = 0; m < 2; m++)
#pragma unroll
                for (int n = 0; n < 4; n++) {
                    mma16816(acc[m][n], ahi[m], bhi[n]);
                    mma16816(acc[m][n], ahi[m], blo[n]);
                    mma16816(acc[m][n], alo[m], bhi[n]);
                }
        }
        __syncthreads();   // all warps done reading B smem before next overwrite

        // ---- epilogue ----
#pragma unroll
        for (int m = 0; m < 2; m++) {
            int row0 = tile * 128 + warp_m * 32 + m * 16 + g;
#pragma unroll
            for (int n = 0; n < 4; n++) {
                int col = warp_n * 32 + n * 8 + t * 2;
                if (r < 8) {
                    float* baseP = &g_hall[(size_t)r * N_NODES * C_DIM];
                    if (row0 < N_NODES)
                        *reinterpret_cast<float2*>(&baseP[(size_t)row0 * C_DIM + col]) =
                            make_float2(acc[m][n][0], acc[m][n][1]);
                    if (row0 + 8 < N_NODES)
                        *reinterpret_cast<float2*>(&baseP[(size_t)(row0 + 8) * C_DIM + col]) =
                            make_float2(acc[m][n][2], acc[m][n][3]);
                } else {
                    float2 bb = *reinterpret_cast<const float2*>(&bias2[col]);
                    if (row0 < N_NODES)
                        *reinterpret_cast<float2*>(&out[(size_t)row0 * C_DIM + col]) =
                            make_float2(acc[m][n][0] + bb.x, acc[m][n][1] + bb.y);
                    if (row0 + 8 < N_NODES)
                        *reinterpret_cast<float2*>(&out[(size_t)(row0 + 8) * C_DIM + col]) =
                            make_float2(acc[m][n][2] + bb.x, acc[m][n][3] + bb.y);
                }
            }
        }
    }
}

// ---------------- layer 2 aggregation: warp per node -------------------------
__global__ __launch_bounds__(256) void agg2_kernel(float* __restrict__ out) {
    int wid  = threadIdx.x >> 5;
    int lane = threadIdx.x & 31;
    int n = blockIdx.x * 8 + wid;
    if (n >= N_NODES) return;
    int beg = g_off[n], end = g_off[n + 1];
    if (beg == end) return;

    float2 acc = make_float2(0.f, 0.f);
    for (int base = beg; base < end; base += 32) {
        int e = base + lane;
        unsigned long long pk = (e < end) ? g_edge[e] : 0ull;
        int m = end - base; if (m > 32) m = 32;
        for (int j = 0; j < m; j++) {
            unsigned long long pj = __shfl_sync(0xffffffffu, pk, j);
            int   rowid = (int)(pj & 0xffffffffu);
            float sc    = __uint_as_float((unsigned)(pj >> 32));
            float2 v = *reinterpret_cast<const float2*>(
                &g_hall[(size_t)rowid * C_DIM + lane * 2]);
            acc.x = fmaf(sc, v.x, acc.x);
            acc.y = fmaf(sc, v.y, acc.y);
        }
    }
    float2* po = reinterpret_cast<float2*>(&out[(size_t)n * C_DIM + lane * 2]);
    float2 cur = *po;
    cur.x += acc.x;
    cur.y += acc.y;
    *po = cur;
}

// ---------------- launch ----------------
extern "C" void kernel_launch(void* const* d_in, const int* in_sizes, int n_in,
                              void* d_out, int out_size) {
    const int*   edge_index = (const int*)d_in[0];
    const int*   edge_type  = (const int*)d_in[1];
    const float* W1         = (const float*)d_in[2];
    const float* root1      = (const float*)d_in[3];
    const float* b1         = (const float*)d_in[4];
    const float* W2         = (const float*)d_in[5];
    const float* root2      = (const float*)d_in[6];
    const float* b2         = (const float*)d_in[7];
    float*       out        = (float*)d_out;

    cudaFuncSetAttribute(gemm_kernel,
                         cudaFuncAttributeMaxDynamicSharedMemorySize, SM_TOT);

    w2prep_kernel<<<(9 * 64 * 64 + 255) / 256, 256>>>(W2, root2);
    zero_cnt_kernel<<<(N_NODES * R_REL + 255) / 256, 256>>>();
    count_kernel<<<(E_EDGES + 255) / 256, 256>>>(edge_index, edge_type);
    scan1_kernel<<<40, 1024>>>();
    scan2_kernel<<<1, 64>>>();
    scan3_kernel<<<40, 1024>>>();
    permute_kernel<<<(E_EDGES + 255) / 256, 256>>>(edge_index, edge_type);
    agg1_kernel<<<5000, 256>>>(W1, root1, b1);
    gemm_kernel<<<TILES, 256, SM_TOT>>>(b2, out);
    agg2_kernel<<<5000, 256>>>(out);
}